// round 17
// baseline (speedup 1.0000x reference)
#include <cuda_runtime.h>
#include <cuda_fp16.h>
#include <cstdint>

typedef unsigned int u32;
typedef unsigned long long u64;

#define F       128
#define NI      31
#define NL      32
#define TMAX    20
#define NGROUP  5            // 5 groups x 4 trees (128 node-cols per group)
#define TILE_M  128
#define NTHREADS 256

// ---- SMEM layout (bytes) ----
// X/W row stride: 72 u32 words (144 fp16, 288B). 72 mod 32 = 8 -> conflict-free LDS.64.
#define STW72  72
#define X_OFF  0             // 128 rows * 288B = 36864 (reused as reduce scratch at the end)
#define W_OFF  36864         // 128 nrows * 288B = 36864
#define L_OFF  73728         // 64 row-pairs * 33 quads * 16B = 33792 (h2 row-pair half-logits)
#define SMEM_BYTES 107520
// L quad layout: quad = pair*33 + tree*8 + colq; quad holds h2 for cols {colq, 8+colq, 16+colq, 24+colq}
// h2 = {row r, row r+8}. Stride 33 == 1 mod 8 -> conflict-free STS.128/LDS.128 octets.

#define H2_HALF 0x38003800u  // fp16x2 {0.5, 0.5}
#define H2_ONE  0x3C003C00u  // fp16x2 {1.0, 1.0}

// __device__ scratch (allocation-free)
__device__ __half g_Wh[NGROUP * 128 * F];  // fp16 HALVED masked weights, k pair-permuted per 16-block

struct alignas(16) ConstBlk {
    float bs[TMAX * 32];     // 0.5*bias, padded to 32 nodes
    u32   lc2[TMAX * 32];    // leaf pairs: h2{base,base}, h2{delta,delta} for class 0
    float wt[TMAX];          // softmax tree weight
};
__device__   ConstBlk g_cb;  // staging (written by prep)
__constant__ ConstBlk c_cb;  // read by main kernel

// ---------------- helpers ----------------
__device__ __forceinline__ u32 smem_u32(const void* p) {
    u32 a;
    asm("{ .reg .u64 t; cvta.to.shared.u64 t, %1; cvt.u32.u64 %0, t; }" : "=r"(a) : "l"(p));
    return a;
}
__device__ __forceinline__ u32 pack_h2(float lo, float hi) {
    u32 r;
    asm("cvt.rn.f16x2.f32 %0, %1, %2;" : "=r"(r) : "f"(hi), "f"(lo));
    return r;
}
__device__ __forceinline__ void cpa16(u32 dst, const void* src) {
    asm volatile("cp.async.cg.shared.global [%0], [%1], 16;" :: "r"(dst), "l"(src) : "memory");
}
#define CP_COMMIT() asm volatile("cp.async.commit_group;" ::: "memory")
template<int N> __device__ __forceinline__ void cp_wait() {
    asm volatile("cp.async.wait_group %0;" :: "n"(N) : "memory");
}
__device__ __forceinline__ void lds_v2(u32& a, u32& b, u32 addr) {
    asm volatile("ld.shared.v2.u32 {%0,%1}, [%2];" : "=r"(a), "=r"(b) : "r"(addr));
}
__device__ __forceinline__ void lds_v4(u32& a, u32& b, u32& c, u32& d, u32 addr) {
    asm volatile("ld.shared.v4.u32 {%0,%1,%2,%3}, [%4];"
                 : "=r"(a), "=r"(b), "=r"(c), "=r"(d) : "r"(addr));
}
__device__ __forceinline__ void sts_v4(u32 addr, u32 a, u32 b, u32 c, u32 d) {
    asm volatile("st.shared.v4.u32 [%0], {%1,%2,%3,%4};"
                 :: "r"(addr), "r"(a), "r"(b), "r"(c), "r"(d) : "memory");
}

// m16n8k16 f16 MMA, fp32 accum.
#define MMA_F16(c, a0, a1, a2, a3, b0, b1) \
    asm volatile("mma.sync.aligned.m16n8k16.row.col.f32.f16.f16.f32 " \
        "{%0,%1,%2,%3}, {%4,%5,%6,%7}, {%8,%9}, {%0,%1,%2,%3};" \
        : "+f"((c)[0]), "+f"((c)[1]), "+f"((c)[2]), "+f"((c)[3]) \
        : "r"(a0), "r"(a1), "r"(a2), "r"(a3), "r"(b0), "r"(b1))

// ---------------- prologue ----------------
// Weights: 4 consecutive k per thread via float4; k-permutation within each
// 16-k block so a lane's B fragment is one LDS.64.
__global__ void prep(const float* __restrict__ sw, const float* __restrict__ fm,
                     const float* __restrict__ sb,
                     const float* __restrict__ ll, const float* __restrict__ tw, int T) {
    int idx = blockIdx.x * 256 + threadIdx.x;
    const int totalv = NGROUP * 128 * 32;   // 20480 float4 chunks
    if (idx < totalv) {
        int c    = idx & 31;                // float4 index within row (k = 4c..4c+3)
        int nrow = (idx >> 5) & 127;
        int g    = idx >> 12;
        int t    = g * 4 + (nrow >> 5);
        int n    = nrow & 31;
        float4 v = make_float4(0.f, 0.f, 0.f, 0.f);
        if (t < T && n < NI) {
            float4 w4 = ((const float4*)(sw + (size_t)(t * NI + n) * F))[c];
            float4 m4 = ((const float4*)(fm + (size_t)t * F))[c];
            v.x = 0.5f * w4.x * m4.x;  v.y = 0.5f * w4.y * m4.y;
            v.z = 0.5f * w4.z * m4.z;  v.w = 0.5f * w4.w * m4.w;
        }
        u32 h01 = pack_h2(v.x, v.y);
        u32 h23 = pack_h2(v.z, v.w);
        int k16c = (c & 3) * 4;
        int base = ((k16c & 7) >> 1) * 4 + ((k16c >> 3) & 1) * 2;
        u32* dst = (u32*)(g_Wh + (size_t)(g * 128 + nrow) * F + (c >> 2) * 16);
        dst[base >> 1]       = h01;
        dst[(base >> 1) + 2] = h23;
    }
    if (idx < TMAX * 32) {   // halved bias, node 31 padded to 0
        int t = idx >> 5, n = idx & 31;
        g_cb.bs[idx] = (t < T && n < NI) ? 0.5f * sb[t * NI + n] : 0.f;
    }
    if (idx < TMAX * 16) {   // leaf lerp constants (class 0), h2-broadcast
        int t = idx >> 4, l = idx & 15;
        float base = 0.f, delta = 0.f;
        if (t < T) {
            float m = -1e30f;
            for (int k = 0; k < T; k++) m = fmaxf(m, tw[k]);
            float den = 0.f;
            for (int k = 0; k < T; k++) den += expf(tw[k] - m);
            float w = expf(tw[t] - m) / den;
            float a0 = ll[(t * NL + 2 * l) * 2 + 0], b0 = ll[(t * NL + 2 * l) * 2 + 1];
            float a1 = ll[(t * NL + 2 * l + 1) * 2 + 0], b1 = ll[(t * NL + 2 * l + 1) * 2 + 1];
            float m0 = fmaxf(a0, b0), m1 = fmaxf(a1, b1);
            float e0 = expf(a0 - m0), f0 = expf(b0 - m0);
            float e1 = expf(a1 - m1), f1 = expf(b1 - m1);
            float p0 = w * e0 / (e0 + f0);
            float p1 = w * e1 / (e1 + f1);
            base = p0; delta = p1 - p0;
        }
        g_cb.lc2[t * 32 + 2 * l + 0] = pack_h2(base, base);
        g_cb.lc2[t * 32 + 2 * l + 1] = pack_h2(delta, delta);
    }
    if (idx < TMAX) {        // tree weights
        float w = 0.f;
        if (idx < T) {
            float m = -1e30f;
            for (int k = 0; k < T; k++) m = fmaxf(m, tw[k]);
            float den = 0.f;
            for (int k = 0; k < T; k++) den += expf(tw[k] - m);
            w = expf(tw[idx] - m) / den;
        }
        g_cb.wt[idx] = w;
    }
}

// ---------------- main fused kernel ----------------
//   [GEMM] [pack row-pair h2 + STS L] sync [cp.async W(g+1)] [h2 SIMD epilogue] -> loop-top sync
__global__ void __launch_bounds__(NTHREADS, 2) forest_mma(
    const float* __restrict__ x, float* __restrict__ out, int B)
{
    extern __shared__ char smem[];
    float* smf = (float*)smem;
    const u32 sbase = smem_u32(smem);
    const int tid  = threadIdx.x;
    const int lane = tid & 31;
    const int wid  = tid >> 5;
    const int gid  = lane >> 2;
    const int tid4 = lane & 3;
    const int warp_m = wid & 1;      // 2 M-groups of 64 rows
    const int warp_n = wid >> 1;     // 4 N-groups of 32 cols (= tree-in-group)
    const int m0 = blockIdx.x * TILE_M;

    // ---- cp.async W group 0 ----
    {
        const __half* src = g_Wh;
        #pragma unroll
        for (int j = 0; j < 8; j++) {
            int i = tid + j * NTHREADS;
            int row = i >> 4, c = i & 15;
            cpa16(sbase + W_OFF + (u32)(row * STW72 * 4) + c * 16, src + row * F + c * 8);
        }
        CP_COMMIT();
    }

    // ---- stage X: LDG float4 -> fp16 pairs at permuted slots ----
    {
        #pragma unroll
        for (int j = 0; j < 16; j++) {
            int i = tid + j * NTHREADS;
            int row = i >> 5, c = i & 31;
            int srow = m0 + row; if (srow >= B) srow = B - 1;
            float4 v = ((const float4*)(x + (size_t)srow * F))[c];
            u32 h01 = pack_h2(v.x, v.y);
            u32 h23 = pack_h2(v.z, v.w);
            int kb = c >> 2, jj = c & 3;
            int wbase = (jj & 1) * 4 + (jj >> 1);
            u32 waddr = sbase + X_OFF + (u32)((row * STW72 + kb * 8 + wbase) * 4);
            asm volatile("st.shared.u32 [%0], %1;" :: "r"(waddr), "r"(h01));
            asm volatile("st.shared.u32 [%0], %1;" :: "r"(waddr + 8), "r"(h23));
        }
    }

    // fragment bases
    const u32 Abase = sbase + X_OFF + (u32)(((warp_m * 64 + gid) * STW72 + tid4 * 2) * 4);
    const u32 Bbase = sbase + W_OFF + (u32)(((warp_n * 32 + gid) * STW72 + tid4 * 2) * 4);

    // reader identity: row-pair rp, tree
    const int rp   = tid & 63;
    const int tree = tid >> 6;             // 0..3 = tree-in-group
    const u32 Rbase = sbase + L_OFF + (u32)((rp * 33 + tree * 8) * 16);
    // actual rows of this pair
    const int r0 = ((rp & 32) << 1) + (((rp >> 3) & 3) << 4) + (rp & 7);
    const int r1 = r0 + 8;

    float oc0lo = 0.f, oc0hi = 0.f, wts = 0.f;

    #pragma unroll 1
    for (int g = 0; g < NGROUP; g++) {
        cp_wait<0>();
        __syncthreads();             // W(g) (+X on g=0) visible; epilogue(g-1) L-reads done

        // ================= GEMM(g): acc starts at 0.5*bias =================
        float acc[4][4][4];
        {
            const float* bsp = c_cb.bs + ((g * 4 + warp_n) * 32 + tid4 * 2);
            #pragma unroll
            for (int nt = 0; nt < 4; nt++) {
                float b0 = bsp[nt * 8], b1 = bsp[nt * 8 + 1];
                #pragma unroll
                for (int mt = 0; mt < 4; mt++) {
                    acc[mt][nt][0] = b0; acc[mt][nt][1] = b1;
                    acc[mt][nt][2] = b0; acc[mt][nt][3] = b1;
                }
            }
        }

        #pragma unroll
        for (int kk = 0; kk < 8; kk++) {
            u32 a[4][4];
            #pragma unroll
            for (int mt = 0; mt < 4; mt++) {
                const u32 rr0 = Abase + (u32)((mt * 16 * STW72 + kk * 8) * 4);
                lds_v2(a[mt][0], a[mt][2], rr0);
                lds_v2(a[mt][1], a[mt][3], rr0 + 8 * STW72 * 4);
            }
            #pragma unroll
            for (int nt = 0; nt < 4; nt++) {
                u32 b0, b1;
                lds_v2(b0, b1, Bbase + (u32)((nt * 8 * STW72 + kk * 8) * 4));
                #pragma unroll
                for (int mt = 0; mt < 4; mt++)
                    MMA_F16(acc[mt][nt], a[mt][0], a[mt][1], a[mt][2], a[mt][3], b0, b1);
            }
        }

        // ---- pack row-pair h2 half-logits, STS.128 (8 per thread, conflict-free) ----
        // h2 = {row r, row r+8}: (acc[q0], acc[q2]) col c; (acc[q1], acc[q3]) col c+1
        #pragma unroll
        for (int mt = 0; mt < 4; mt++) {
            const int pair = warp_m * 32 + mt * 8 + gid;
            u32 qa0 = pack_h2(acc[mt][0][0], acc[mt][0][2]);
            u32 qa1 = pack_h2(acc[mt][1][0], acc[mt][1][2]);
            u32 qa2 = pack_h2(acc[mt][2][0], acc[mt][2][2]);
            u32 qa3 = pack_h2(acc[mt][3][0], acc[mt][3][2]);
            u32 qb0 = pack_h2(acc[mt][0][1], acc[mt][0][3]);
            u32 qb1 = pack_h2(acc[mt][1][1], acc[mt][1][3]);
            u32 qb2 = pack_h2(acc[mt][2][1], acc[mt][2][3]);
            u32 qb3 = pack_h2(acc[mt][3][1], acc[mt][3][3]);
            u32 qaddr = sbase + L_OFF + (u32)((pair * 33 + warp_n * 8 + tid4 * 2) * 16);
            sts_v4(qaddr,      qa0, qa1, qa2, qa3);   // colq = tid4*2   (cols nt*8 + tid4*2)
            sts_v4(qaddr + 16, qb0, qb1, qb2, qb3);   // colq = tid4*2+1
        }

        __syncthreads();             // merged: W(g) reads done (buffer free) + L(g) visible

        // prefetch W(g+1) (overlaps epilogue)
        if (g < NGROUP - 1) {
            const __half* src = g_Wh + (size_t)(g + 1) * 128 * F;
            #pragma unroll
            for (int j = 0; j < 8; j++) {
                int i = tid + j * NTHREADS;
                int row = i >> 4, c = i & 15;
                cpa16(sbase + W_OFF + (u32)(row * STW72 * 4) + c * 16, src + row * F + c * 8);
            }
            CP_COMMIT();
        }

        // ---- h2 SIMD epilogue: 1 (row-pair, tree) task per thread ----
        {
            const int t = g * 4 + tree;
            const u32* lc2 = c_cb.lc2 + t * 32;
            u32 s2[32];
            #pragma unroll
            for (int cq = 0; cq < 8; cq++) {
                u32 w0, w1, w2, w3;
                lds_v4(w0, w1, w2, w3, Rbase + (u32)(cq * 16));
                s2[0 * 8 + cq] = w0; s2[1 * 8 + cq] = w1;
                s2[2 * 8 + cq] = w2; s2[3 * 8 + cq] = w3;
            }
            // sigmoid: values are l/2 -> s = 0.5*tanh + 0.5  (both rows at once)
            #pragma unroll
            for (int n = 0; n < NI; n++) {
                u32 th;
                asm("tanh.approx.f16x2 %0, %1;" : "=r"(th) : "r"(s2[n]));
                asm("fma.rn.f16x2 %0, %1, %2, %3;" : "=r"(s2[n]) : "r"(th), "r"(H2_HALF), "r"(H2_HALF));
            }
            u32 Pn2[NI];
            Pn2[0] = H2_ONE;
            #pragma unroll
            for (int i = 0; i < 15; i++) {
                u32 pr;
                asm("mul.rn.f16x2 %0, %1, %2;" : "=r"(pr) : "r"(Pn2[i]), "r"(s2[i]));
                Pn2[2 * i + 2] = pr;
                asm("sub.rn.f16x2 %0, %1, %2;" : "=r"(Pn2[2 * i + 1]) : "r"(Pn2[i]), "r"(pr));
            }
            u32 a2a = 0u, a2b = 0u;   // two h2 accumulators (halve sum rounding)
            #pragma unroll
            for (int l = 0; l < 16; l += 2) {
                u32 u0, u1;
                asm("fma.rn.f16x2 %0, %1, %2, %3;" : "=r"(u0)
                    : "r"(s2[15 + l]), "r"(lc2[2 * l + 1]), "r"(lc2[2 * l]));
                asm("fma.rn.f16x2 %0, %1, %2, %3;" : "=r"(a2a)
                    : "r"(Pn2[15 + l]), "r"(u0), "r"(a2a));
                asm("fma.rn.f16x2 %0, %1, %2, %3;" : "=r"(u1)
                    : "r"(s2[16 + l]), "r"(lc2[2 * l + 3]), "r"(lc2[2 * l + 2]));
                asm("fma.rn.f16x2 %0, %1, %2, %3;" : "=r"(a2b)
                    : "r"(Pn2[16 + l]), "r"(u1), "r"(a2b));
            }
            u32 a2;
            asm("add.rn.f16x2 %0, %1, %2;" : "=r"(a2) : "r"(a2a), "r"(a2b));
            __half2 hv = *(__half2*)&a2;
            oc0lo += __low2float(hv);
            oc0hi += __high2float(hv);
            wts   += c_cb.wt[t];
        }
    }

    // ---- write per-(row, tree) partials, reduce 4 trees per row ----
    __syncthreads();
    smf[(r0 * 4 + tree) * 2 + 0] = oc0lo;
    smf[(r0 * 4 + tree) * 2 + 1] = wts - oc0lo;
    smf[(r1 * 4 + tree) * 2 + 0] = oc0hi;
    smf[(r1 * 4 + tree) * 2 + 1] = wts - oc0hi;
    __syncthreads();
    if (tid < TILE_M) {
        float a0 = 0.f, a1 = 0.f;
        #pragma unroll
        for (int e = 0; e < 4; e++) {
            a0 += smf[(tid * 4 + e) * 2 + 0];
            a1 += smf[(tid * 4 + e) * 2 + 1];
        }
        int row = m0 + tid;
        if (row < B) ((float2*)out)[row] = make_float2(a0, a1);
    }
}

// ---------------- launch ----------------
extern "C" void kernel_launch(void* const* d_in, const int* in_sizes, int n_in,
                              void* d_out, int out_size)
{
    const float* x  = (const float*)d_in[0];  // [B, 128]
    const float* sw = (const float*)d_in[1];  // [T, 31, 128]
    const float* sb = (const float*)d_in[2];  // [T, 31]
    const float* ll = (const float*)d_in[3];  // [T, 32, 2]
    const float* tw = (const float*)d_in[4];  // [T]
    const float* fm = (const float*)d_in[5];  // [T, 128]

    int T = in_sizes[4];
    if (T > TMAX) T = TMAX;
    int B = in_sizes[0] / F;

    cudaFuncSetAttribute(forest_mma, cudaFuncAttributeMaxDynamicSharedMemorySize, SMEM_BYTES);

    prep<<<(NGROUP * 128 * 32 + 255) / 256, 256>>>(sw, fm, sb, ll, tw, T);

    // single merged constant upload (D2D async: graph-capturable)
    void* p = nullptr;
    cudaGetSymbolAddress(&p, g_cb);
    cudaMemcpyToSymbolAsync(c_cb, p, sizeof(ConstBlk), 0,
                            cudaMemcpyDeviceToDevice, 0);

    forest_mma<<<(B + TILE_M - 1) / TILE_M, NTHREADS, SMEM_BYTES>>>(x, (float*)d_out, B);
}